// round 13
// baseline (speedup 1.0000x reference)
#include <cuda_runtime.h>

#define FULLMASK 0xffffffffu

// Single fused kernel, grid = n/32 blocks (1024 for N=32768).
// HOT PHASE (all 8 warps): pure streaming reduce, identical structure to the
// K1 kernel that measured 6.2 TB/s standalone: per patch 16 x LDG.128 upfront
// (grouped 64B chunks), 8 shfl + 4 STS, nothing else. Each warp does 4 patches.
// TAIL (warp 0 after __syncthreads): thread-per-patch scalar router math
// (verified in R8/R12), 32 lanes = 32 patches, zero cross-lane ops.
__global__ void __launch_bounds__(256) router_kernel(
    const float* __restrict__ patch,
    const float* __restrict__ keys,
    const float* __restrict__ p_temp,
    const float* __restrict__ p_beta,
    const float* __restrict__ p_thr,
    float* __restrict__ out,
    int n_patches)
{
    __shared__ float s_keys[16][32];    // broadcast reads in tail
    __shared__ float s_raw[32][33];     // [patch-in-block][channel], pad 33

    const int tid  = threadIdx.x;
    const int wid  = tid >> 5;
    const int lane = tid & 31;

    // Stage keys (read only by tail warp, after the syncthreads below)
    for (int i = tid; i < 16 * 32; i += 256)
        s_keys[i >> 5][i & 31] = keys[i];

    const int block_base = blockIdx.x * 32;
    const int lidx = (lane >> 2) * 16 + (lane & 3);   // grouped 64B-chunk index

    // =================== HOT PHASE: 4 patches per warp ===================
#pragma unroll 1
    for (int i = 0; i < 4; i++) {
        const int lp = wid * 4 + i;                // local patch 0..31
        const int n  = block_base + lp;
        if (n < n_patches) {
            const float4* p4 = reinterpret_cast<const float4*>(patch) + (size_t)n * 512;
            float4 v[16];
#pragma unroll
            for (int t = 0; t < 16; t++) {
                const int p = t >> 2, q = t & 3;
                v[t] = p4[p * 128 + lidx + 4 * q];
            }
#pragma unroll
            for (int p = 0; p < 4; p++) {
                float a = 0.0f;
#pragma unroll
                for (int q = 0; q < 4; q++) {
                    const float4 x = v[p * 4 + q];
                    a += (x.x + x.y) + (x.z + x.w);
                }
                a += __shfl_xor_sync(FULLMASK, a, 1);
                a += __shfl_xor_sync(FULLMASK, a, 2);
                if ((lane & 3) == 0)
                    s_raw[lp][p * 8 + (lane >> 2)] = a;   // raw channel sum
            }
        }
    }

    __syncthreads();   // all 32 patches' channel sums ready

    // =================== TAIL: warp 0, 1 patch per lane, scalar ===================
    if (wid != 0) return;

    const int n = block_base + lane;
    if (n >= n_patches) return;

    const float logit_temp = __ldg(p_temp);
    const float mask_beta  = __ldg(p_beta);
    const float thr_base   = __ldg(p_thr);

    // Load channel sums (stride-33 rows: conflict-free across lanes)
    float emb[32];
#pragma unroll
    for (int c = 0; c < 32; c++) emb[c] = s_raw[lane][c];

    // L2 norm
    float sq = 0.0f;
#pragma unroll
    for (int c = 0; c < 32; c++) sq = fmaf(emb[c], emb[c], sq);
    const float denom = fmaxf(sqrtf(sq), 64.0f * 1e-12f);

    // Logits + softmax over 16 experts
    float w[16];
    float m = -1e30f;
#pragma unroll
    for (int e = 0; e < 16; e++) {
        float dot = 0.0f;
#pragma unroll
        for (int c = 0; c < 32; c++)
            dot = fmaf(emb[c], s_keys[e][c], dot);
        w[e] = (dot / denom) / logit_temp + 1e-8f;
        m = fmaxf(m, w[e]);
    }
    float S = 0.0f;
#pragma unroll
    for (int e = 0; e < 16; e++) { w[e] = __expf(w[e] - m); S += w[e]; }
    const float invS = 1.0f / S;
#pragma unroll
    for (int e = 0; e < 16; e++) w[e] *= invS;

    // Top-5 values via selection (values only)
    float t[16];
#pragma unroll
    for (int e = 0; e < 16; e++) t[e] = w[e];
    float top[5];
#pragma unroll
    for (int k = 0; k < 5; k++) {
        float best = t[0]; int bi = 0;
#pragma unroll
        for (int e = 1; e < 16; e++)
            if (t[e] > best) { best = t[e]; bi = e; }
        top[k] = best;
        t[bi] = -1.0f;
    }
    const float s0   = top[0];
    const float rest = (top[1] + top[2] + top[3] + top[4]) * 0.25f;
    const float kth  = top[3];                         // 4th largest

    // Moments & entropy
    float sum = 0.0f, ent = 0.0f;
#pragma unroll
    for (int e = 0; e < 16; e++) {
        sum += w[e];
        ent -= w[e] * __logf(w[e] + 1e-18f);
    }
    const float meanw = sum * (1.0f / 16.0f);
    float var = 0.0f;
#pragma unroll
    for (int e = 0; e < 16; e++) {
        const float d = w[e] - meanw;
        var = fmaf(d, d, var);
    }
    const float stdw = sqrtf(var * (1.0f / 15.0f));    // ddof=1

    // Adaptive threshold
    const float maxc = 1.0f - s0;
    const float entc = 1.0f - ent * (1.0f / 2.7725887222397811f);   // 1/log(16)
    float gap = (s0 - rest) / (s0 + 1e-8f);
    gap = fminf(fmaxf(gap, 0.0f), 1.0f);
    const float af = 0.4f * maxc + 0.3f * entc + 0.3f * gap;
    float adaptive = thr_base * (0.5f + af);
    const float min_thr = fmaxf(0.05f, meanw - 0.5f * stdw);
    const float max_thr = fminf(0.7f, s0 - 0.1f * stdw);
    adaptive = fminf(fmaxf(adaptive, min_thr), max_thr);
    adaptive = fminf(adaptive, kth * 0.9f);

    // Soft mask + renormalize
    float wf[16];
    float swf = 0.0f;
#pragma unroll
    for (int e = 0; e < 16; e++) {
        const float x  = (mask_beta + 1e-8f) * (w[e] - adaptive);
        const float sm = 1.0f / (1.0f + __expf(-x));
        wf[e] = w[e] * sm;
        swf += wf[e];
    }
    const float inv = 1.0f / fmaxf(swf, 1e-8f);

    float4* o4 = reinterpret_cast<float4*>(out + (size_t)n * 16);
#pragma unroll
    for (int j = 0; j < 4; j++) {
        float4 r;
        r.x = wf[j * 4 + 0] * inv; r.y = wf[j * 4 + 1] * inv;
        r.z = wf[j * 4 + 2] * inv; r.w = wf[j * 4 + 3] * inv;
        o4[j] = r;
    }
}

extern "C" void kernel_launch(void* const* d_in, const int* in_sizes, int n_in,
                              void* d_out, int out_size) {
    const float* patch = (const float*)d_in[0];
    const float* keys  = (const float*)d_in[1];
    const float* temp  = (const float*)d_in[2];
    const float* beta  = (const float*)d_in[3];
    const float* thr   = (const float*)d_in[4];
    float* out = (float*)d_out;

    const int n_patches = in_sizes[0] / (32 * 8 * 8);
    const int blocks = (n_patches + 31) / 32;   // 32 patches per block, grid ~1024
    router_kernel<<<blocks, 256>>>(patch, keys, temp, beta, thr, out, n_patches);
}

// round 14
// speedup vs baseline: 1.0728x; 1.0728x over previous
#include <cuda_runtime.h>

#define FULLMASK 0xffffffffu
#define MAX_PATCHES 32768

// Scratch: per-patch raw channel sums (mean*64), 32768 x 32 floats = 4MB.
__device__ float g_emb[MAX_PATCHES * 32];

// ============================================================================
// K1: pure streaming reduction — BYTE-IDENTICAL to the R5 kernel measured at
// ~42.4us / 78% DRAM. One warp per patch; 16 x LDG.128 grouped (4-lane 64B
// chunks); epilogue = 2 shfl + predicated STG per pass.
// ============================================================================
__global__ void __launch_bounds__(256) reduce_kernel(
    const float* __restrict__ patch, int n_patches)
{
    const int wid  = threadIdx.x >> 5;
    const int lane = threadIdx.x & 31;
    const int n = blockIdx.x * 8 + wid;
    if (n >= n_patches) return;

    const float4* p4 = reinterpret_cast<const float4*>(patch) + (size_t)n * 512;

    float4 v[16];
#pragma unroll
    for (int t = 0; t < 16; t++) {
        const int p = t >> 2, q = t & 3;
        const int idx = p * 128 + (lane >> 2) * 16 + (lane & 3) + 4 * q;
        v[t] = p4[idx];
    }

#pragma unroll
    for (int p = 0; p < 4; p++) {
        float a = 0.0f;
#pragma unroll
        for (int q = 0; q < 4; q++) {
            const float4 x = v[p * 4 + q];
            a += (x.x + x.y) + (x.z + x.w);
        }
        a += __shfl_xor_sync(FULLMASK, a, 1);
        a += __shfl_xor_sync(FULLMASK, a, 2);
        if ((lane & 3) == 0)
            g_emb[n * 32 + p * 8 + (lane >> 2)] = a;   // raw channel sum
    }
}

// ============================================================================
// K2: 4 threads per patch (131072 threads -> ~28 warps/SM, vs 7 for 1/patch).
// Lane-group of 4: lane r loads channels 8r..8r+7 (coalesced, non-redundant),
// computes partial dots for ALL 16 experts, folds with 2 shfl_xor per value.
// Then every lane holds the full w[16] and runs the scalar stats redundantly
// (no further communication). Lane r writes output float4 r -> coalesced.
// ============================================================================
__global__ void __launch_bounds__(256) finalize_kernel(
    const float* __restrict__ keys,
    const float* __restrict__ p_temp,
    const float* __restrict__ p_beta,
    const float* __restrict__ p_thr,
    float* __restrict__ out,
    int n_patches)
{
    __shared__ float s_keys[16][33];   // pad 33: lanes r=0..3 hit distinct banks

    const int tid = threadIdx.x;
    for (int i = tid; i < 16 * 32; i += 256)
        s_keys[i >> 5][i & 31] = keys[i];
    __syncthreads();

    const int gt = blockIdx.x * 256 + tid;
    const int n  = gt >> 2;            // patch
    const int r  = gt & 3;             // lane-in-group (== lane&3 within warp)
    if (n >= n_patches) return;

    const float logit_temp = __ldg(p_temp);
    const float mask_beta  = __ldg(p_beta);
    const float thr_base   = __ldg(p_thr);

    // ---- Load this lane's 8 channels (2 x LDG.128, warp fully coalesced) ----
    const float4* g4 = reinterpret_cast<const float4*>(&g_emb[n * 32]) + r * 2;
    const float4 a0 = g4[0];
    const float4 a1 = g4[1];
    float emb[8] = {a0.x, a0.y, a0.z, a0.w, a1.x, a1.y, a1.z, a1.w};

    // ---- Partial squared-norm + fold over the 4-lane group ----
    float sq = 0.0f;
#pragma unroll
    for (int c = 0; c < 8; c++) sq = fmaf(emb[c], emb[c], sq);
    sq += __shfl_xor_sync(FULLMASK, sq, 1);
    sq += __shfl_xor_sync(FULLMASK, sq, 2);
    const float denom = fmaxf(sqrtf(sq), 64.0f * 1e-12f);

    // ---- Partial dots for all 16 experts over this lane's 8 channels ----
    float w[16];
#pragma unroll
    for (int e = 0; e < 16; e++) {
        float d = 0.0f;
#pragma unroll
        for (int c = 0; c < 8; c++)
            d = fmaf(emb[c], s_keys[e][r * 8 + c], d);
        // fold partials: all 4 lanes end with the full dot
        d += __shfl_xor_sync(FULLMASK, d, 1);
        d += __shfl_xor_sync(FULLMASK, d, 2);
        w[e] = (d / denom) / logit_temp + 1e-8f;
    }

    // ---- Softmax over 16 (scalar; identical on all 4 lanes) ----
    float m = w[0];
#pragma unroll
    for (int e = 1; e < 16; e++) m = fmaxf(m, w[e]);
    float S = 0.0f;
#pragma unroll
    for (int e = 0; e < 16; e++) { w[e] = __expf(w[e] - m); S += w[e]; }
    const float invS = 1.0f / S;
#pragma unroll
    for (int e = 0; e < 16; e++) w[e] *= invS;

    // ---- Top-5 via selection with exclusion bitmask (no t[16] copy) ----
    float top[5];
    unsigned used = 0;
#pragma unroll
    for (int k = 0; k < 5; k++) {
        float best = -1.0f; int bi = 0;
#pragma unroll
        for (int e = 0; e < 16; e++) {
            const bool ok = !((used >> e) & 1u) && (w[e] > best);
            if (ok) { best = w[e]; bi = e; }
        }
        top[k] = best;
        used |= 1u << bi;
    }
    const float s0   = top[0];
    const float rest = (top[1] + top[2] + top[3] + top[4]) * 0.25f;
    const float kth  = top[3];                         // 4th largest

    // ---- Moments & entropy ----
    float sum = 0.0f, ent = 0.0f;
#pragma unroll
    for (int e = 0; e < 16; e++) {
        sum += w[e];
        ent -= w[e] * __logf(w[e] + 1e-18f);
    }
    const float meanw = sum * (1.0f / 16.0f);
    float var = 0.0f;
#pragma unroll
    for (int e = 0; e < 16; e++) {
        const float d = w[e] - meanw;
        var = fmaf(d, d, var);
    }
    const float stdw = sqrtf(var * (1.0f / 15.0f));    // ddof=1

    // ---- Adaptive threshold ----
    const float maxc = 1.0f - s0;
    const float entc = 1.0f - ent * (1.0f / 2.7725887222397811f);   // 1/log(16)
    float gap = (s0 - rest) / (s0 + 1e-8f);
    gap = fminf(fmaxf(gap, 0.0f), 1.0f);
    const float af = 0.4f * maxc + 0.3f * entc + 0.3f * gap;
    float adaptive = thr_base * (0.5f + af);
    const float min_thr = fmaxf(0.05f, meanw - 0.5f * stdw);
    const float max_thr = fminf(0.7f, s0 - 0.1f * stdw);
    adaptive = fminf(fmaxf(adaptive, min_thr), max_thr);
    adaptive = fminf(adaptive, kth * 0.9f);

    // ---- Soft mask + renorm; this lane writes its quarter (coalesced) ----
    float wf[16];
    float swf = 0.0f;
#pragma unroll
    for (int e = 0; e < 16; e++) {
        const float x  = (mask_beta + 1e-8f) * (w[e] - adaptive);
        const float sm = 1.0f / (1.0f + __expf(-x));
        wf[e] = w[e] * sm;
        swf += wf[e];
    }
    const float inv = 1.0f / fmaxf(swf, 1e-8f);

    float4 o;
    o.x = wf[r * 4 + 0] * inv; o.y = wf[r * 4 + 1] * inv;
    o.z = wf[r * 4 + 2] * inv; o.w = wf[r * 4 + 3] * inv;
    reinterpret_cast<float4*>(out + (size_t)n * 16)[r] = o;
}

extern "C" void kernel_launch(void* const* d_in, const int* in_sizes, int n_in,
                              void* d_out, int out_size) {
    const float* patch = (const float*)d_in[0];
    const float* keys  = (const float*)d_in[1];
    const float* temp  = (const float*)d_in[2];
    const float* beta  = (const float*)d_in[3];
    const float* thr   = (const float*)d_in[4];
    float* out = (float*)d_out;

    int n_patches = in_sizes[0] / (32 * 8 * 8);
    if (n_patches > MAX_PATCHES) n_patches = MAX_PATCHES;

    const int blocks1 = (n_patches + 7) / 8;          // K1: 8 patches / block
    reduce_kernel<<<blocks1, 256>>>(patch, n_patches);

    const int blocks2 = (n_patches * 4 + 255) / 256;  // K2: 4 threads / patch
    finalize_kernel<<<blocks2, 256>>>(keys, temp, beta, thr, out, n_patches);
}